// round 3
// baseline (speedup 1.0000x reference)
#include <cuda_runtime.h>

// Sliding-window minimum, window = [t, t+256] (257 elems), 'last' padding.
// out[b,t] = min_{i=t..t+256} sig[b, min(i, T-1)]
//
// Chunk-16 prefix/suffix decomposition: window len 257 = (16-m) + 15*16 + (m+1)
// for phase m = t%16 -> out = min( suf16[t], 15 full-chunk mins, pre16[t+256] ).
//
// Per thread: 2 front-batched LDGs, then ONLY the scan each half actually needs:
//   low half  (pos 0..255):   suffix scan  -> sSuf;  chunk min = suf at p%16==0
//   high half (pos 256..511): prefix scan  -> sPreHi; chunk min = pre at p%16==15
// = 8 SHFLs/thread (two independent depth-4 chains), then a depth-4 fmin tree.

#define BT 256  // outputs per block / threads per block

__global__ __launch_bounds__(BT) void always_window_min(
    const float* __restrict__ sig, float* __restrict__ out, int T)
{
    const int b    = blockIdx.y;
    const int t0   = blockIdx.x * BT;
    const int p    = threadIdx.x;
    const int lane = p & 31;
    const int seg  = lane & 15;              // position within 16-chunk

    __shared__ float sSuf[BT];               // suffix-min in chunk, pos [0,256)
    __shared__ float sPreHi[BT];             // prefix-min in chunk, pos [256,512)
    __shared__ float sChunk[2 * BT / 16];    // 32 full-chunk mins

    const float* row = sig + (size_t)b * T;

    // Front-batch both loads (MLP=2). 'last' padding clamp.
    int g0 = t0 + p;        g0 = g0 < T - 1 ? g0 : T - 1;
    int g1 = t0 + p + BT;   g1 = g1 < T - 1 ? g1 : T - 1;
    float x0 = __ldg(row + g0);
    float x1 = __ldg(row + g1);

    // Two independent 16-segmented scans (depth 4 each, interleaved by HW):
    //   suf over x0 (low half), pre over x1 (high half).
    float suf = x0, pre = x1;
    #pragma unroll
    for (int d = 1; d < 16; d <<= 1) {
        float dn = __shfl_down_sync(0xffffffffu, suf, d);
        if (seg < 16 - d) suf = fminf(suf, dn);
        float up = __shfl_up_sync(0xffffffffu, pre, d);
        if (seg >= d) pre = fminf(pre, up);
    }

    sSuf[p]   = suf;
    sPreHi[p] = pre;
    if (seg == 0)  sChunk[p >> 4]        = suf;  // low-half chunk min
    if (seg == 15) sChunk[16 + (p >> 4)] = pre;  // high-half chunk min
    __syncthreads();

    const int c = p >> 4;                    // own chunk (0..15)
    // 15 full chunks c+1 .. c+15 (indices <= 30). Broadcast LDS reads.
    float v0  = sChunk[c + 1],  v1  = sChunk[c + 2],  v2  = sChunk[c + 3];
    float v3  = sChunk[c + 4],  v4  = sChunk[c + 5],  v5  = sChunk[c + 6];
    float v6  = sChunk[c + 7],  v7  = sChunk[c + 8],  v8  = sChunk[c + 9];
    float v9  = sChunk[c + 10], v10 = sChunk[c + 11], v11 = sChunk[c + 12];
    float v12 = sChunk[c + 13], v13 = sChunk[c + 14], v14 = sChunk[c + 15];

    float a0 = fminf(v0,  v1),  a1 = fminf(v2,  v3);
    float a2 = fminf(v4,  v5),  a3 = fminf(v6,  v7);
    float a4 = fminf(v8,  v9),  a5 = fminf(v10, v11);
    float a6 = fminf(v12, v13), a7 = fminf(v14, sPreHi[p]);  // pre at p+256
    float b0 = fminf(a0, a1), b1 = fminf(a2, a3);
    float b2 = fminf(a4, a5), b3 = fminf(a6, a7);
    float c0 = fminf(b0, b1), c1 = fminf(b2, b3);
    float m  = fminf(fminf(c0, c1), sSuf[p]);

    out[(size_t)b * T + t0 + p] = m;
}

extern "C" void kernel_launch(void* const* d_in, const int* in_sizes, int n_in,
                              void* d_out, int out_size)
{
    const float* sig = (const float*)d_in[0];
    float* out = (float*)d_out;

    const int T = 8192;                      // per reference setup_inputs
    const int B = in_sizes[0] / T;           // = 4

    dim3 grid(T / BT, B);
    always_window_min<<<grid, BT>>>(sig, out, T);
}